// round 9
// baseline (speedup 1.0000x reference)
#include <cuda_runtime.h>
#include <cuda_bf16.h>
#include <cstdint>

// RoPE2D encoder: output = [cos_2d (HW x 128) ; sin_2d (HW x 128)], fp32.
// H = W = 512, DIM = 128. Channels [0,64) depend only on x, [64,128) only on y.
// Single fused kernel, STG.256 stores (st.global.cs.v8.b32, sm_10x):
//   lane q covers 8 floats; lanes 0-15 = row p, lanes 16-31 = row p+1, so one
//   warp store instruction writes a contiguous 1024B 2-row pair.
//   Values computed analytically: sincosf for the initial angle, then an
//   angle-addition rotation (step = 2 positions) across 8 iterations = 16 rows.

#define RP_H 512
#define RP_W 512
#define RP_HW (RP_H * RP_W)
#define ROWS_PER_WARP 16   // 8 iterations x 2 rows

__device__ __forceinline__ void stg256_cs(float* p, const float* v) {
    asm volatile("st.global.cs.v8.b32 [%0], {%1,%2,%3,%4,%5,%6,%7,%8};"
                 :: "l"(p),
                    "r"(__float_as_uint(v[0])), "r"(__float_as_uint(v[1])),
                    "r"(__float_as_uint(v[2])), "r"(__float_as_uint(v[3])),
                    "r"(__float_as_uint(v[4])), "r"(__float_as_uint(v[5])),
                    "r"(__float_as_uint(v[6])), "r"(__float_as_uint(v[7]))
                 : "memory");
}

// Warp: fixed `which` (cos/sin), 16 consecutive positions p0..p0+15 (same y,
// 16 | 512). Lane q: rowhalf = q>>4 (row p0+2i+rowhalf), c8 = q&15 = 8-float
// chunk of the 128-channel row. c8<8 -> x-half (freq idx 8*(c8&3)+j),
// c8>=8 -> y-half. x-lanes rotate by 2f per iteration; y-lanes by 0.
__global__ void __launch_bounds__(256) rope2d_fused(float* __restrict__ out,
                                                    const float* __restrict__ inv_freq_x,
                                                    const float* __restrict__ inv_freq_y) {
    unsigned warp_in_block = threadIdx.x >> 5;
    unsigned q             = threadIdx.x & 31u;
    unsigned gw    = blockIdx.x * 8u + warp_in_block;   // 0..32767
    unsigned which = gw >> 14;                          // 0 = cos, 1 = sin
    unsigned rp    = gw & 16383u;
    unsigned p0    = rp * ROWS_PER_WARP;
    unsigned y     = p0 >> 9;
    unsigned x0    = p0 & 511u;

    unsigned rowhalf = q >> 4;        // 0 or 1: which row of the 1024B pair
    unsigned c8      = q & 15u;       // 8-float chunk within the row
    bool is_x = (c8 < 8u);

    // freq indices for this chunk: (8*c8 + j) mod 32 = 8*(c8&3) + j, j=0..7
    const float4* tf = reinterpret_cast<const float4*>(is_x ? inv_freq_x : inv_freq_y);
    unsigned fb = (c8 & 3u) * 2u;
    float4 fa = __ldg(tf + fb);
    float4 fbv = __ldg(tf + fb + 1u);
    float fr[8] = {fa.x, fa.y, fa.z, fa.w, fbv.x, fbv.y, fbv.z, fbv.w};

    float pos  = is_x ? (float)(x0 + rowhalf) : (float)y;
    float step = is_x ? 2.0f : 0.0f;           // y-lanes: identity rotation

    float c[8], s[8], cf[8], sf[8];
    #pragma unroll
    for (int j = 0; j < 8; j++) {
        sincosf(pos * fr[j], &s[j], &c[j]);
        sincosf(step * fr[j], &sf[j], &cf[j]);
    }

    float* ptr = out + (size_t)which * (RP_HW * 128u)
                     + (size_t)p0 * 128u + q * 8u;

    #pragma unroll
    for (int i = 0; i < ROWS_PER_WARP / 2; i++) {
        float val[8];
        #pragma unroll
        for (int j = 0; j < 8; j++) val[j] = which ? s[j] : c[j];
        stg256_cs(ptr + (size_t)i * 256u, val);   // 1024B per warp instruction

        if (i < ROWS_PER_WARP / 2 - 1) {
            #pragma unroll
            for (int j = 0; j < 8; j++) {
                float cn = fmaf(c[j], cf[j], -s[j] * sf[j]);
                float sn = fmaf(s[j], cf[j],  c[j] * sf[j]);
                c[j] = cn;
                s[j] = sn;
            }
        }
    }
}

extern "C" void kernel_launch(void* const* d_in, const int* in_sizes, int n_in,
                              void* d_out, int out_size) {
    const float* inv_freq_x = (const float*)d_in[1];
    const float* inv_freq_y = (const float*)d_in[2];
    float* out = (float*)d_out;

    // 32768 warps = 2 (which) x 16384 row-pair groups; 8 warps/block -> 4096 blocks
    rope2d_fused<<<4096, 256>>>(out, inv_freq_x, inv_freq_y);
}